// round 13
// baseline (speedup 1.0000x reference)
#include <cuda_runtime.h>
#include <math.h>

#define T_STEPS 128
#define B_SZ    256
#define NI      1024
#define NH      2048
#define NO      256
#define MROWS   (T_STEPS * B_SZ)   // 32768

// ---------------- packed f32x2 helpers (sm_100+) ----------------------------
__device__ __forceinline__ void unpack2(unsigned long long v, float& x, float& y)
{
    asm("mov.b64 {%0, %1}, %2;" : "=f"(x), "=f"(y) : "l"(v));
}
#define FMA2(acc, s1, s2) \
    asm("fma.rn.f32x2 %0, %1, %2, %0;" : "+l"(acc) : "l"(s1), "l"(s2))

// ---------------- reference sigmoid: Eigen/Cephes pexp with fmaf ------------
__device__ __forceinline__ float expf_cephes(float x)
{
    x = fminf(fmaxf(x, -88.723164f), 88.723164f);
    float m = floorf(fmaf(x, 1.44269504088896341f, 0.5f));
    float r = fmaf(m, -0.693359375f, x);
    r = fmaf(m, 2.12194440e-4f, r);
    float r2 = __fmul_rn(r, r);
    float r3 = __fmul_rn(r2, r);
    float y  = fmaf(1.9875691500E-4f, r, 1.3981999507E-3f);
    float y1 = fmaf(4.1665795894E-2f, r, 1.6666665459E-1f);
    float y2 = __fadd_rn(r, 1.0f);
    y  = fmaf(y, r, 8.3334519073E-3f);
    y1 = fmaf(y1, r, 5.0000001201E-1f);
    y  = fmaf(y, r3, y1);
    y  = fmaf(y, r2, y2);
    int e = (int)m;
    return __fmul_rn(y, __int_as_float((e + 127) << 23));
}

__device__ __forceinline__ float sigmoid_ref(float z)
{
    float e = expf_cephes(-z);
    return __fdiv_rn(1.0f, __fadd_rn(1.0f, e));
}

// ---------------- tiny probe kernel (shifts ncu capture to GEMM1) -----------
__global__ void probe_kernel(float* p) { *p = 0.0f; }

// ---------------- staging helper: one 8-k group into a tile buffer ----------
__device__ __forceinline__ void stage_group(float* sA, float* sB,
                                            int kk, int rowA,
                                            float4 va0, float4 va1,
                                            float4 vb0, float4 vb1,
                                            float4 vb2, float4 vb3)
{
    float* pA = sA + (size_t)kk * 256 + 2 * rowA;
    *reinterpret_cast<float2*>(pA + 0 * 256) = make_float2(va0.x, va0.x);
    *reinterpret_cast<float2*>(pA + 1 * 256) = make_float2(va0.y, va0.y);
    *reinterpret_cast<float2*>(pA + 2 * 256) = make_float2(va0.z, va0.z);
    *reinterpret_cast<float2*>(pA + 3 * 256) = make_float2(va0.w, va0.w);
    *reinterpret_cast<float2*>(pA + 4 * 256) = make_float2(va1.x, va1.x);
    *reinterpret_cast<float2*>(pA + 5 * 256) = make_float2(va1.y, va1.y);
    *reinterpret_cast<float2*>(pA + 6 * 256) = make_float2(va1.z, va1.z);
    *reinterpret_cast<float2*>(pA + 7 * 256) = make_float2(va1.w, va1.w);
    float* pB = sB + (size_t)kk * 256 + rowA;
    pB[0 * 256] = vb0.x; pB[1 * 256] = vb0.y;
    pB[2 * 256] = vb0.z; pB[3 * 256] = vb0.w;
    pB[4 * 256] = vb1.x; pB[5 * 256] = vb1.y;
    pB[6 * 256] = vb1.z; pB[7 * 256] = vb1.w;
    float* pB2 = pB + 128;
    pB2[0 * 256] = vb2.x; pB2[1 * 256] = vb2.y;
    pB2[2 * 256] = vb2.z; pB2[3 * 256] = vb2.w;
    pB2[4 * 256] = vb3.x; pB2[5 * 256] = vb3.y;
    pB2[6 * 256] = vb3.z; pB2[7 * 256] = vb3.w;
}

// ---------------- fp32 chain GEMM, 128x256 block, 8x16 thread tile ----------
// out[r][n] = chain_k fma.rn(A[r][k], B[n][k]), k ascending, single acc ->
// bit-identical to the validated chain. BKT=32 (syncs halved vs R10);
// staging split mid-iteration so live staging registers stay at 6 float4.
// MODE 0: grid.x 0..7 -> B0=W1, sigmoid -> out0 ; 8..15 -> B1=Wr, relu -> out1
// MODE 1: grid.x == 0 -> B0=W2, bias only -> out0
#define BKT 32
#define BM  128
#define BN  256

template <int MODE>
__global__ __launch_bounds__(256)
void gemm_big(const float* __restrict__ A,
              const float* __restrict__ B0, const float* __restrict__ B1,
              int K,
              const float* __restrict__ bias0, const float* __restrict__ bias1,
              float* __restrict__ out0, float* __restrict__ out1)
{
    extern __shared__ float sh[];
    float* sAd = sh;                       // [2][BKT][2*BM]  (A rows duplicated)
    float* sB  = sh + 2 * BKT * 2 * BM;    // [2][BKT][BN]

    const int t     = threadIdx.x;
    const int mBase = blockIdx.y * BM;
    const int nBase = blockIdx.x * BN;

    bool sig;
    const float* Bsel;
    const float* bs;
    float* o;
    int nrow, ostride;
    if (MODE == 0) {
        sig     = (nBase < NH);
        Bsel    = sig ? B0 : B1;
        nrow    = sig ? nBase : (nBase - NH);
        bs      = sig ? bias0 : bias1;
        o       = sig ? out0 : out1;
        ostride = NH;
    } else {
        sig = false; Bsel = B0; nrow = nBase; bs = bias0; o = out0; ostride = NO;
    }

    // staging assignment: thread t covers A row (t>>1) and B rows (t>>1),
    // (t>>1)+128, at k-groups (t&1)*8 and (t&1)*8+16 within each 32-k tile.
    const int rowA = t >> 1;
    const int kg   = (t & 1) * 8;
    const size_t aOff  = (size_t)(mBase + rowA) * K + kg;
    const size_t bOff0 = (size_t)(nrow + rowA) * K + kg;
    const size_t bOff1 = (size_t)(nrow + rowA + 128) * K + kg;

    // prologue: stage tile 0 fully (both k-groups)
    {
        float4 va0 = *reinterpret_cast<const float4*>(A + aOff);
        float4 va1 = *reinterpret_cast<const float4*>(A + aOff + 4);
        float4 vb0 = *reinterpret_cast<const float4*>(Bsel + bOff0);
        float4 vb1 = *reinterpret_cast<const float4*>(Bsel + bOff0 + 4);
        float4 vb2 = *reinterpret_cast<const float4*>(Bsel + bOff1);
        float4 vb3 = *reinterpret_cast<const float4*>(Bsel + bOff1 + 4);
        stage_group(sAd, sB, kg, rowA, va0, va1, vb0, vb1, vb2, vb3);
        va0 = *reinterpret_cast<const float4*>(A + aOff + 16);
        va1 = *reinterpret_cast<const float4*>(A + aOff + 20);
        vb0 = *reinterpret_cast<const float4*>(Bsel + bOff0 + 16);
        vb1 = *reinterpret_cast<const float4*>(Bsel + bOff0 + 20);
        vb2 = *reinterpret_cast<const float4*>(Bsel + bOff1 + 16);
        vb3 = *reinterpret_cast<const float4*>(Bsel + bOff1 + 20);
        stage_group(sAd, sB, kg + 16, rowA, va0, va1, vb0, vb1, vb2, vb3);
    }
    __syncthreads();

    const int tx = t & 15, ty = t >> 4;
    const int m0 = ty * 8;

    unsigned long long acc[8][8];
#pragma unroll
    for (int i = 0; i < 8; i++)
#pragma unroll
        for (int j = 0; j < 8; j++) acc[i][j] = 0ULL;

    const int KT = K / BKT;
    const int bufStride = BKT * 256;
#pragma unroll 1
    for (int s = 0; s < KT; s++) {
        const int buf = s & 1;
        const bool more = (s + 1 < KT);
        const float* sAb = sAd + (size_t)buf * bufStride;
        const float* sBb = sB  + (size_t)buf * bufStride;
        float* sAn = sAd + (size_t)(buf ^ 1) * bufStride;
        float* sBn = sB  + (size_t)(buf ^ 1) * bufStride;
        const size_t k1 = (size_t)(s + 1) * BKT;

        float4 va0, va1, vb0, vb1, vb2, vb3;
        if (more) {                       // prefetch group 0 of next tile
            va0 = *reinterpret_cast<const float4*>(A + aOff + k1);
            va1 = *reinterpret_cast<const float4*>(A + aOff + k1 + 4);
            vb0 = *reinterpret_cast<const float4*>(Bsel + bOff0 + k1);
            vb1 = *reinterpret_cast<const float4*>(Bsel + bOff0 + k1 + 4);
            vb2 = *reinterpret_cast<const float4*>(Bsel + bOff1 + k1);
            vb3 = *reinterpret_cast<const float4*>(Bsel + bOff1 + k1 + 4);
        }

#pragma unroll
        for (int kk = 0; kk < BKT / 2; kk++) {
            const float* pa = sAb + kk * 256 + 2 * m0;
            ulonglong2 A0 = *reinterpret_cast<const ulonglong2*>(pa);
            ulonglong2 A1 = *reinterpret_cast<const ulonglong2*>(pa + 4);
            ulonglong2 A2 = *reinterpret_cast<const ulonglong2*>(pa + 8);
            ulonglong2 A3 = *reinterpret_cast<const ulonglong2*>(pa + 12);
            const float* pb = sBb + kk * 256 + 2 * tx;
            unsigned long long bb[8];
#pragma unroll
            for (int j = 0; j < 8; j++)
                bb[j] = *reinterpret_cast<const unsigned long long*>(pb + 32 * j);
            unsigned long long aa[8];
            aa[0] = A0.x; aa[1] = A0.y; aa[2] = A1.x; aa[3] = A1.y;
            aa[4] = A2.x; aa[5] = A2.y; aa[6] = A3.x; aa[7] = A3.y;
#pragma unroll
            for (int i = 0; i < 8; i++)
#pragma unroll
                for (int j = 0; j < 8; j++)
                    FMA2(acc[i][j], bb[j], aa[i]);
        }

        if (more) {                       // store group 0, prefetch group 1
            stage_group(sAn, sBn, kg, rowA, va0, va1, vb0, vb1, vb2, vb3);
            va0 = *reinterpret_cast<const float4*>(A + aOff + k1 + 16);
            va1 = *reinterpret_cast<const float4*>(A + aOff + k1 + 20);
            vb0 = *reinterpret_cast<const float4*>(Bsel + bOff0 + k1 + 16);
            vb1 = *reinterpret_cast<const float4*>(Bsel + bOff0 + k1 + 20);
            vb2 = *reinterpret_cast<const float4*>(Bsel + bOff1 + k1 + 16);
            vb3 = *reinterpret_cast<const float4*>(Bsel + bOff1 + k1 + 20);
        }

#pragma unroll
        for (int kk = BKT / 2; kk < BKT; kk++) {
            const float* pa = sAb + kk * 256 + 2 * m0;
            ulonglong2 A0 = *reinterpret_cast<const ulonglong2*>(pa);
            ulonglong2 A1 = *reinterpret_cast<const ulonglong2*>(pa + 4);
            ulonglong2 A2 = *reinterpret_cast<const ulonglong2*>(pa + 8);
            ulonglong2 A3 = *reinterpret_cast<const ulonglong2*>(pa + 12);
            const float* pb = sBb + kk * 256 + 2 * tx;
            unsigned long long bb[8];
#pragma unroll
            for (int j = 0; j < 8; j++)
                bb[j] = *reinterpret_cast<const unsigned long long*>(pb + 32 * j);
            unsigned long long aa[8];
            aa[0] = A0.x; aa[1] = A0.y; aa[2] = A1.x; aa[3] = A1.y;
            aa[4] = A2.x; aa[5] = A2.y; aa[6] = A3.x; aa[7] = A3.y;
#pragma unroll
            for (int i = 0; i < 8; i++)
#pragma unroll
                for (int j = 0; j < 8; j++)
                    FMA2(acc[i][j], bb[j], aa[i]);
        }

        if (more) {                       // store group 1, switch buffers
            stage_group(sAn, sBn, kg + 16, rowA, va0, va1, vb0, vb1, vb2, vb3);
            __syncthreads();
        }
    }

    // epilogue: bias + activation + store (col pairs {2tx + 32j})
    float2 bv[8];
#pragma unroll
    for (int j = 0; j < 8; j++)
        bv[j] = *reinterpret_cast<const float2*>(&bs[nrow + 2 * tx + 32 * j]);

#pragma unroll
    for (int i = 0; i < 8; i++) {
        float* orow = o + (size_t)(mBase + m0 + i) * ostride + nrow + 2 * tx;
#pragma unroll
        for (int j = 0; j < 8; j++) {
            float lo, hi;
            unpack2(acc[i][j], lo, hi);
            lo = __fadd_rn(lo, bv[j].x);
            hi = __fadd_rn(hi, bv[j].y);
            if (MODE == 0) {
                if (sig) { lo = sigmoid_ref(lo); hi = sigmoid_ref(hi); }
                else     { lo = fmaxf(lo, 0.0f); hi = fmaxf(hi, 0.0f); }
            }
            *reinterpret_cast<float2*>(orow + 32 * j) = make_float2(lo, hi);
        }
    }
}

// ---------------- layer-1 recurrence (float4, strict rn, in-place; R10) -----
__global__ void rec1_kernel(float4* cf, float4* fm)
{
    const int i = blockIdx.x * blockDim.x + threadIdx.x;   // < B*NH/4
    float4 syn = make_float4(0.f, 0.f, 0.f, 0.f);
    float4 mem = make_float4(0.f, 0.f, 0.f, 0.f);
    size_t off = i;
    const size_t stride = (size_t)B_SZ * NH / 4;
#pragma unroll 2
    for (int t = 0; t < T_STEPS; t++, off += stride) {
        float4 c = cf[off];
        float4 f = fm[off];
        float4 spk;
        syn.x = __fadd_rn(__fmul_rn(f.x, syn.x), __fmul_rn(__fsub_rn(1.f, f.x), c.x));
        syn.y = __fadd_rn(__fmul_rn(f.y, syn.y), __fmul_rn(__fsub_rn(1.f, f.y), c.y));
        syn.z = __fadd_rn(__fmul_rn(f.z, syn.z), __fmul_rn(__fsub_rn(1.f, f.z), c.z));
        syn.w = __fadd_rn(__fmul_rn(f.w, syn.w), __fmul_rn(__fsub_rn(1.f, f.w), c.w));
        spk.x = (__fsub_rn(mem.x, 1.0f) > 0.0f) ? 1.f : 0.f;
        spk.y = (__fsub_rn(mem.y, 1.0f) > 0.0f) ? 1.f : 0.f;
        spk.z = (__fsub_rn(mem.z, 1.0f) > 0.0f) ? 1.f : 0.f;
        spk.w = (__fsub_rn(mem.w, 1.0f) > 0.0f) ? 1.f : 0.f;
        mem.x = __fsub_rn(__fadd_rn(__fmul_rn(0.5f, mem.x), syn.x), spk.x);
        mem.y = __fsub_rn(__fadd_rn(__fmul_rn(0.5f, mem.y), syn.y), spk.y);
        mem.z = __fsub_rn(__fadd_rn(__fmul_rn(0.5f, mem.z), syn.z), spk.z);
        mem.w = __fsub_rn(__fadd_rn(__fmul_rn(0.5f, mem.w), syn.w), spk.w);
        cf[off] = spk;
        fm[off] = mem;
    }
}

// ---------------- layer-2 recurrence (R10) -----------------------------------
__global__ void rec2_kernel(float* is, float* __restrict__ mo)
{
    const int i = blockIdx.x * blockDim.x + threadIdx.x;   // < B*NO
    float syn = 0.f, mem = 0.f;
    size_t off = i;
#pragma unroll 1
    for (int t = 0; t < T_STEPS; t++, off += (size_t)B_SZ * NO) {
        float inp = is[off];
        float m = __fsub_rn(mem, 1.0f);
        float spk = (m > 0.0f) ? 1.f : 0.f;
        syn = __fadd_rn(__fmul_rn(0.5f, syn), inp);
        mem = __fsub_rn(__fadd_rn(__fmul_rn(0.5f, mem), syn), spk);
        is[off] = spk;
        mo[off] = mem;
    }
}

// ---------------- launch ------------------------------------------------------
extern "C" void kernel_launch(void* const* d_in, const int* in_sizes, int n_in,
                              void* d_out, int out_size)
{
    const float* x  = (const float*)d_in[0];
    const float* W1 = (const float*)d_in[1];
    const float* b1 = (const float*)d_in[2];
    const float* Wr = (const float*)d_in[3];
    const float* br = (const float*)d_in[4];
    const float* W2 = (const float*)d_in[5];
    const float* b2 = (const float*)d_in[6];

    float* out = (float*)d_out;
    float* cand_spk1 = out;                                     // [T*B, NH]
    float* forg_mem1 = out + (size_t)MROWS * NH;                // [T*B, NH]
    float* inp2_spk2 = out + 2 * (size_t)MROWS * NH;            // [T*B, NO]
    float* mem2      = inp2_spk2 + (size_t)MROWS * NO;          // [T*B, NO]

    const int smemBytes = 2 * BKT * (2 * BM + BN) * (int)sizeof(float);  // 128 KB
    static bool attrSet = false;
    if (!attrSet) {
        cudaFuncSetAttribute(gemm_big<0>,
                             cudaFuncAttributeMaxDynamicSharedMemorySize, smemBytes);
        cudaFuncSetAttribute(gemm_big<1>,
                             cudaFuncAttributeMaxDynamicSharedMemorySize, smemBytes);
        attrSet = true;
    }

    // 0) probe launches (1-3): shift ncu capture (launch #4) onto GEMM1
    probe_kernel<<<1, 1>>>(inp2_spk2);
    probe_kernel<<<1, 1>>>(inp2_spk2);
    probe_kernel<<<1, 1>>>(inp2_spk2);

    // 1) GEMM1: cand = sigmoid(x@W1.T+b1), forget = relu(x@Wr.T+br)
    gemm_big<0><<<dim3(2 * NH / BN, MROWS / BM), 256, smemBytes>>>(
        x, W1, Wr, NI, b1, br, cand_spk1, forg_mem1);

    // 2) layer-1 scan (in-place, float4; R10-proven)
    rec1_kernel<<<(B_SZ * NH / 4) / 256, 256>>>(
        (float4*)cand_spk1, (float4*)forg_mem1);

    // 3) GEMM2: inp2 = spk1@W2.T + b2 -> spk2 region
    gemm_big<1><<<dim3(NO / BN, MROWS / BM), 256, smemBytes>>>(
        cand_spk1, W2, nullptr, NH, b2, nullptr, inp2_spk2, nullptr);

    // 4) layer-2 scan (in-place: inp2->spk2; R10-proven)
    rec2_kernel<<<(B_SZ * NO) / 256, 256>>>(inp2_spk2, mem2);

    (void)in_sizes; (void)n_in; (void)out_size;
}

// round 14
// speedup vs baseline: 1.0282x; 1.0282x over previous
#include <cuda_runtime.h>
#include <math.h>

#define T_STEPS 128
#define B_SZ    256
#define NI      1024
#define NH      2048
#define NO      256
#define MROWS   (T_STEPS * B_SZ)   // 32768

// ---------------- packed f32x2 helpers (sm_100+) ----------------------------
__device__ __forceinline__ void unpack2(unsigned long long v, float& x, float& y)
{
    asm("mov.b64 {%0, %1}, %2;" : "=f"(x), "=f"(y) : "l"(v));
}
#define FMA2(acc, s1, s2) \
    asm("fma.rn.f32x2 %0, %1, %2, %0;" : "+l"(acc) : "l"(s1), "l"(s2))

// ---------------- reference sigmoid: Eigen/Cephes pexp with fmaf ------------
__device__ __forceinline__ float expf_cephes(float x)
{
    x = fminf(fmaxf(x, -88.723164f), 88.723164f);
    float m = floorf(fmaf(x, 1.44269504088896341f, 0.5f));
    float r = fmaf(m, -0.693359375f, x);
    r = fmaf(m, 2.12194440e-4f, r);
    float r2 = __fmul_rn(r, r);
    float r3 = __fmul_rn(r2, r);
    float y  = fmaf(1.9875691500E-4f, r, 1.3981999507E-3f);
    float y1 = fmaf(4.1665795894E-2f, r, 1.6666665459E-1f);
    float y2 = __fadd_rn(r, 1.0f);
    y  = fmaf(y, r, 8.3334519073E-3f);
    y1 = fmaf(y1, r, 5.0000001201E-1f);
    y  = fmaf(y, r3, y1);
    y  = fmaf(y, r2, y2);
    int e = (int)m;
    return __fmul_rn(y, __int_as_float((e + 127) << 23));
}

__device__ __forceinline__ float sigmoid_ref(float z)
{
    float e = expf_cephes(-z);
    return __fdiv_rn(1.0f, __fadd_rn(1.0f, e));
}

// ---------------- fp32 chain GEMM, 128x256 block, 8x16 thread tile ----------
// out[r][n] = chain_k fma.rn(A[r][k], B[n][k]), k ascending, single acc ->
// bit-identical to the validated chain. R10-proven configuration.
// MODE 0: grid.x 0..7 -> B0=W1, sigmoid -> out0 ; 8..15 -> B1=Wr, relu -> out1
// MODE 1: grid.x == 0 -> B0=W2, bias only -> out0
#define BKT 16
#define BM  128
#define BN  256

template <int MODE>
__global__ __launch_bounds__(256)
void gemm_big(const float* __restrict__ A,
              const float* __restrict__ B0, const float* __restrict__ B1,
              int K,
              const float* __restrict__ bias0, const float* __restrict__ bias1,
              float* __restrict__ out0, float* __restrict__ out1)
{
    extern __shared__ float sh[];
    float* sAd = sh;                       // [2][BKT][2*BM]  (A rows duplicated)
    float* sB  = sh + 2 * BKT * 2 * BM;    // [2][BKT][BN]

    const int t     = threadIdx.x;
    const int mBase = blockIdx.y * BM;
    const int nBase = blockIdx.x * BN;

    bool sig;
    const float* Bsel;
    const float* bs;
    float* o;
    int nrow, ostride;
    if (MODE == 0) {
        sig     = (nBase < NH);
        Bsel    = sig ? B0 : B1;
        nrow    = sig ? nBase : (nBase - NH);
        bs      = sig ? bias0 : bias1;
        o       = sig ? out0 : out1;
        ostride = NH;
    } else {
        sig = false; Bsel = B0; nrow = nBase; bs = bias0; o = out0; ostride = NO;
    }

    const int rowA = t >> 1;
    const int kseg = (t & 1) * 8;
    const size_t aOff  = (size_t)(mBase + rowA) * K + kseg;
    const size_t bOff0 = (size_t)(nrow + rowA) * K + kseg;
    const size_t bOff1 = (size_t)(nrow + rowA + 128) * K + kseg;

    float4 va0 = *reinterpret_cast<const float4*>(A + aOff);
    float4 va1 = *reinterpret_cast<const float4*>(A + aOff + 4);
    float4 vb0 = *reinterpret_cast<const float4*>(Bsel + bOff0);
    float4 vb1 = *reinterpret_cast<const float4*>(Bsel + bOff0 + 4);
    float4 vb2 = *reinterpret_cast<const float4*>(Bsel + bOff1);
    float4 vb3 = *reinterpret_cast<const float4*>(Bsel + bOff1 + 4);

    {
        float* pA = sAd + (size_t)kseg * 256 + 2 * rowA;
        *reinterpret_cast<float2*>(pA + 0 * 256) = make_float2(va0.x, va0.x);
        *reinterpret_cast<float2*>(pA + 1 * 256) = make_float2(va0.y, va0.y);
        *reinterpret_cast<float2*>(pA + 2 * 256) = make_float2(va0.z, va0.z);
        *reinterpret_cast<float2*>(pA + 3 * 256) = make_float2(va0.w, va0.w);
        *reinterpret_cast<float2*>(pA + 4 * 256) = make_float2(va1.x, va1.x);
        *reinterpret_cast<float2*>(pA + 5 * 256) = make_float2(va1.y, va1.y);
        *reinterpret_cast<float2*>(pA + 6 * 256) = make_float2(va1.z, va1.z);
        *reinterpret_cast<float2*>(pA + 7 * 256) = make_float2(va1.w, va1.w);
        float* pB = sB + (size_t)kseg * 256 + rowA;
        pB[0 * 256] = vb0.x; pB[1 * 256] = vb0.y;
        pB[2 * 256] = vb0.z; pB[3 * 256] = vb0.w;
        pB[4 * 256] = vb1.x; pB[5 * 256] = vb1.y;
        pB[6 * 256] = vb1.z; pB[7 * 256] = vb1.w;
        float* pB2 = pB + 128;
        pB2[0 * 256] = vb2.x; pB2[1 * 256] = vb2.y;
        pB2[2 * 256] = vb2.z; pB2[3 * 256] = vb2.w;
        pB2[4 * 256] = vb3.x; pB2[5 * 256] = vb3.y;
        pB2[6 * 256] = vb3.z; pB2[7 * 256] = vb3.w;
    }
    __syncthreads();

    const int tx = t & 15, ty = t >> 4;
    const int m0 = ty * 8;

    unsigned long long acc[8][8];
#pragma unroll
    for (int i = 0; i < 8; i++)
#pragma unroll
        for (int j = 0; j < 8; j++) acc[i][j] = 0ULL;

    const int KT = K / BKT;
    const int bufStride = BKT * 256;
#pragma unroll 1
    for (int s = 0; s < KT; s++) {
        const int buf = s & 1;
        const bool more = (s + 1 < KT);
        if (more) {
            const size_t k1 = (size_t)(s + 1) * BKT;
            va0 = *reinterpret_cast<const float4*>(A + aOff + k1);
            va1 = *reinterpret_cast<const float4*>(A + aOff + k1 + 4);
            vb0 = *reinterpret_cast<const float4*>(Bsel + bOff0 + k1);
            vb1 = *reinterpret_cast<const float4*>(Bsel + bOff0 + k1 + 4);
            vb2 = *reinterpret_cast<const float4*>(Bsel + bOff1 + k1);
            vb3 = *reinterpret_cast<const float4*>(Bsel + bOff1 + k1 + 4);
        }

        const float* sAb = sAd + (size_t)buf * bufStride;
        const float* sBb = sB  + (size_t)buf * bufStride;

#pragma unroll
        for (int kk = 0; kk < BKT; kk++) {
            const float* pa = sAb + kk * 256 + 2 * m0;
            ulonglong2 A0 = *reinterpret_cast<const ulonglong2*>(pa);
            ulonglong2 A1 = *reinterpret_cast<const ulonglong2*>(pa + 4);
            ulonglong2 A2 = *reinterpret_cast<const ulonglong2*>(pa + 8);
            ulonglong2 A3 = *reinterpret_cast<const ulonglong2*>(pa + 12);
            const float* pb = sBb + kk * 256 + 2 * tx;
            unsigned long long bb[8];
#pragma unroll
            for (int j = 0; j < 8; j++)
                bb[j] = *reinterpret_cast<const unsigned long long*>(pb + 32 * j);

            unsigned long long aa[8];
            aa[0] = A0.x; aa[1] = A0.y; aa[2] = A1.x; aa[3] = A1.y;
            aa[4] = A2.x; aa[5] = A2.y; aa[6] = A3.x; aa[7] = A3.y;
#pragma unroll
            for (int i = 0; i < 8; i++)
#pragma unroll
                for (int j = 0; j < 8; j++)
                    FMA2(acc[i][j], bb[j], aa[i]);
        }

        if (more) {
            const int nb = buf ^ 1;
            float* pA = sAd + (size_t)nb * bufStride + kseg * 256 + 2 * rowA;
            *reinterpret_cast<float2*>(pA + 0 * 256) = make_float2(va0.x, va0.x);
            *reinterpret_cast<float2*>(pA + 1 * 256) = make_float2(va0.y, va0.y);
            *reinterpret_cast<float2*>(pA + 2 * 256) = make_float2(va0.z, va0.z);
            *reinterpret_cast<float2*>(pA + 3 * 256) = make_float2(va0.w, va0.w);
            *reinterpret_cast<float2*>(pA + 4 * 256) = make_float2(va1.x, va1.x);
            *reinterpret_cast<float2*>(pA + 5 * 256) = make_float2(va1.y, va1.y);
            *reinterpret_cast<float2*>(pA + 6 * 256) = make_float2(va1.z, va1.z);
            *reinterpret_cast<float2*>(pA + 7 * 256) = make_float2(va1.w, va1.w);
            float* pB = sB + (size_t)nb * bufStride + kseg * 256 + rowA;
            pB[0 * 256] = vb0.x; pB[1 * 256] = vb0.y;
            pB[2 * 256] = vb0.z; pB[3 * 256] = vb0.w;
            pB[4 * 256] = vb1.x; pB[5 * 256] = vb1.y;
            pB[6 * 256] = vb1.z; pB[7 * 256] = vb1.w;
            float* pB2 = pB + 128;
            pB2[0 * 256] = vb2.x; pB2[1 * 256] = vb2.y;
            pB2[2 * 256] = vb2.z; pB2[3 * 256] = vb2.w;
            pB2[4 * 256] = vb3.x; pB2[5 * 256] = vb3.y;
            pB2[6 * 256] = vb3.z; pB2[7 * 256] = vb3.w;
            __syncthreads();
        }
    }

    float2 bv[8];
#pragma unroll
    for (int j = 0; j < 8; j++)
        bv[j] = *reinterpret_cast<const float2*>(&bs[nrow + 2 * tx + 32 * j]);

#pragma unroll
    for (int i = 0; i < 8; i++) {
        float* orow = o + (size_t)(mBase + m0 + i) * ostride + nrow + 2 * tx;
#pragma unroll
        for (int j = 0; j < 8; j++) {
            float lo, hi;
            unpack2(acc[i][j], lo, hi);
            lo = __fadd_rn(lo, bv[j].x);
            hi = __fadd_rn(hi, bv[j].y);
            if (MODE == 0) {
                if (sig) { lo = sigmoid_ref(lo); hi = sigmoid_ref(hi); }
                else     { lo = fmaxf(lo, 0.0f); hi = fmaxf(hi, 0.0f); }
            }
            *reinterpret_cast<float2*>(orow + 32 * j) = make_float2(lo, hi);
        }
    }
}

// ---------------- layer-1 recurrence (float4, strict rn, in-place; R10) -----
__global__ void rec1_kernel(float4* cf, float4* fm)
{
    const int i = blockIdx.x * blockDim.x + threadIdx.x;   // < B*NH/4
    float4 syn = make_float4(0.f, 0.f, 0.f, 0.f);
    float4 mem = make_float4(0.f, 0.f, 0.f, 0.f);
    size_t off = i;
    const size_t stride = (size_t)B_SZ * NH / 4;
#pragma unroll 2
    for (int t = 0; t < T_STEPS; t++, off += stride) {
        float4 c = cf[off];
        float4 f = fm[off];
        float4 spk;
        syn.x = __fadd_rn(__fmul_rn(f.x, syn.x), __fmul_rn(__fsub_rn(1.f, f.x), c.x));
        syn.y = __fadd_rn(__fmul_rn(f.y, syn.y), __fmul_rn(__fsub_rn(1.f, f.y), c.y));
        syn.z = __fadd_rn(__fmul_rn(f.z, syn.z), __fmul_rn(__fsub_rn(1.f, f.z), c.z));
        syn.w = __fadd_rn(__fmul_rn(f.w, syn.w), __fmul_rn(__fsub_rn(1.f, f.w), c.w));
        spk.x = (__fsub_rn(mem.x, 1.0f) > 0.0f) ? 1.f : 0.f;
        spk.y = (__fsub_rn(mem.y, 1.0f) > 0.0f) ? 1.f : 0.f;
        spk.z = (__fsub_rn(mem.z, 1.0f) > 0.0f) ? 1.f : 0.f;
        spk.w = (__fsub_rn(mem.w, 1.0f) > 0.0f) ? 1.f : 0.f;
        mem.x = __fsub_rn(__fadd_rn(__fmul_rn(0.5f, mem.x), syn.x), spk.x);
        mem.y = __fsub_rn(__fadd_rn(__fmul_rn(0.5f, mem.y), syn.y), spk.y);
        mem.z = __fsub_rn(__fadd_rn(__fmul_rn(0.5f, mem.z), syn.z), spk.z);
        mem.w = __fsub_rn(__fadd_rn(__fmul_rn(0.5f, mem.w), syn.w), spk.w);
        cf[off] = spk;
        fm[off] = mem;
    }
}

// ---------------- layer-2 recurrence (R10) -----------------------------------
__global__ void rec2_kernel(float* is, float* __restrict__ mo)
{
    const int i = blockIdx.x * blockDim.x + threadIdx.x;   // < B*NO
    float syn = 0.f, mem = 0.f;
    size_t off = i;
#pragma unroll 1
    for (int t = 0; t < T_STEPS; t++, off += (size_t)B_SZ * NO) {
        float inp = is[off];
        float m = __fsub_rn(mem, 1.0f);
        float spk = (m > 0.0f) ? 1.f : 0.f;
        syn = __fadd_rn(__fmul_rn(0.5f, syn), inp);
        mem = __fsub_rn(__fadd_rn(__fmul_rn(0.5f, mem), syn), spk);
        is[off] = spk;
        mo[off] = mem;
    }
}

// ---------------- launch ------------------------------------------------------
extern "C" void kernel_launch(void* const* d_in, const int* in_sizes, int n_in,
                              void* d_out, int out_size)
{
    const float* x  = (const float*)d_in[0];
    const float* W1 = (const float*)d_in[1];
    const float* b1 = (const float*)d_in[2];
    const float* Wr = (const float*)d_in[3];
    const float* br = (const float*)d_in[4];
    const float* W2 = (const float*)d_in[5];
    const float* b2 = (const float*)d_in[6];

    float* out = (float*)d_out;
    float* cand_spk1 = out;                                     // [T*B, NH]
    float* forg_mem1 = out + (size_t)MROWS * NH;                // [T*B, NH]
    float* inp2_spk2 = out + 2 * (size_t)MROWS * NH;            // [T*B, NO]
    float* mem2      = inp2_spk2 + (size_t)MROWS * NO;          // [T*B, NO]

    const int smemBytes = 2 * BKT * (2 * BM + BN) * (int)sizeof(float);  // 64 KB
    static bool attrSet = false;
    if (!attrSet) {
        cudaFuncSetAttribute(gemm_big<0>,
                             cudaFuncAttributeMaxDynamicSharedMemorySize, smemBytes);
        cudaFuncSetAttribute(gemm_big<1>,
                             cudaFuncAttributeMaxDynamicSharedMemorySize, smemBytes);
        attrSet = true;
    }

    // 1) GEMM1: cand = sigmoid(x@W1.T+b1), forget = relu(x@Wr.T+br)
    gemm_big<0><<<dim3(2 * NH / BN, MROWS / BM), 256, smemBytes>>>(
        x, W1, Wr, NI, b1, br, cand_spk1, forg_mem1);

    // 2) layer-1 scan (in-place, float4)
    rec1_kernel<<<(B_SZ * NH / 4) / 256, 256>>>(
        (float4*)cand_spk1, (float4*)forg_mem1);

    // 3) GEMM2: inp2 = spk1@W2.T + b2 -> spk2 region
    gemm_big<1><<<dim3(NO / BN, MROWS / BM), 256, smemBytes>>>(
        cand_spk1, W2, nullptr, NH, b2, nullptr, inp2_spk2, nullptr);

    // 4) layer-2 scan (in-place: inp2->spk2)
    rec2_kernel<<<(B_SZ * NO) / 256, 256>>>(inp2_spk2, mem2);

    (void)in_sizes; (void)n_in; (void)out_size;
}

// round 15
// speedup vs baseline: 1.0663x; 1.0370x over previous
#include <cuda_runtime.h>
#include <math.h>

#define T_STEPS 128
#define B_SZ    256
#define NI      1024
#define NH      2048
#define NO      256
#define MROWS   (T_STEPS * B_SZ)   // 32768

// ---------------- packed f32x2 helpers (sm_100+) ----------------------------
__device__ __forceinline__ void unpack2(unsigned long long v, float& x, float& y)
{
    asm("mov.b64 {%0, %1}, %2;" : "=f"(x), "=f"(y) : "l"(v));
}
#define FMA2(acc, a, b) \
    asm("fma.rn.f32x2 %0, %1, %2, %0;" : "+l"(acc) : "l"(a), "l"(b))

// ---------------- reference sigmoid: Eigen/Cephes pexp with fmaf ------------
__device__ __forceinline__ float expf_cephes(float x)
{
    x = fminf(fmaxf(x, -88.723164f), 88.723164f);
    float m = floorf(fmaf(x, 1.44269504088896341f, 0.5f));
    float r = fmaf(m, -0.693359375f, x);
    r = fmaf(m, 2.12194440e-4f, r);
    float r2 = __fmul_rn(r, r);
    float r3 = __fmul_rn(r2, r);
    float y  = fmaf(1.9875691500E-4f, r, 1.3981999507E-3f);
    float y1 = fmaf(4.1665795894E-2f, r, 1.6666665459E-1f);
    float y2 = __fadd_rn(r, 1.0f);
    y  = fmaf(y, r, 8.3334519073E-3f);
    y1 = fmaf(y1, r, 5.0000001201E-1f);
    y  = fmaf(y, r3, y1);
    y  = fmaf(y, r2, y2);
    int e = (int)m;
    return __fmul_rn(y, __int_as_float((e + 127) << 23));
}

__device__ __forceinline__ float sigmoid_ref(float z)
{
    float e = expf_cephes(-z);
    return __fdiv_rn(1.0f, __fadd_rn(1.0f, e));
}

// ---------------- fp32 chain GEMM, 128x256 block, 8x16 thread tile ----------
// out[r][n] = chain_k fma.rn(A[r][k], B[n][k]), k ascending, single acc ->
// bit-identical to the validated chain (R10 configuration, byte-exact).
// MODE 0: grid.x 0..7 -> B0=W1, sigmoid -> out0 ; 8..15 -> B1=Wr, relu -> out1
// MODE 1: grid.x == 0 -> B0=W2, bias only -> out0
#define BKT 16
#define BM  128
#define BN  256

template <int MODE>
__global__ __launch_bounds__(256)
void gemm_big(const float* __restrict__ A,
              const float* __restrict__ B0, const float* __restrict__ B1,
              int K,
              const float* __restrict__ bias0, const float* __restrict__ bias1,
              float* __restrict__ out0, float* __restrict__ out1)
{
    extern __shared__ float sh[];
    float* sAd = sh;                       // [2][BKT][2*BM]  (A rows duplicated)
    float* sB  = sh + 2 * BKT * 2 * BM;    // [2][BKT][BN]

    const int t     = threadIdx.x;
    const int mBase = blockIdx.y * BM;
    const int nBase = blockIdx.x * BN;

    bool sig;
    const float* Bsel;
    const float* bs;
    float* o;
    int nrow, ostride;
    if (MODE == 0) {
        sig     = (nBase < NH);
        Bsel    = sig ? B0 : B1;
        nrow    = sig ? nBase : (nBase - NH);
        bs      = sig ? bias0 : bias1;
        o       = sig ? out0 : out1;
        ostride = NH;
    } else {
        sig = false; Bsel = B0; nrow = nBase; bs = bias0; o = out0; ostride = NO;
    }

    const int rowA = t >> 1;
    const int kseg = (t & 1) * 8;
    const size_t aOff  = (size_t)(mBase + rowA) * K + kseg;
    const size_t bOff0 = (size_t)(nrow + rowA) * K + kseg;
    const size_t bOff1 = (size_t)(nrow + rowA + 128) * K + kseg;

    float4 va0 = *reinterpret_cast<const float4*>(A + aOff);
    float4 va1 = *reinterpret_cast<const float4*>(A + aOff + 4);
    float4 vb0 = *reinterpret_cast<const float4*>(Bsel + bOff0);
    float4 vb1 = *reinterpret_cast<const float4*>(Bsel + bOff0 + 4);
    float4 vb2 = *reinterpret_cast<const float4*>(Bsel + bOff1);
    float4 vb3 = *reinterpret_cast<const float4*>(Bsel + bOff1 + 4);

    {
        float* pA = sAd + (size_t)kseg * 256 + 2 * rowA;
        *reinterpret_cast<float2*>(pA + 0 * 256) = make_float2(va0.x, va0.x);
        *reinterpret_cast<float2*>(pA + 1 * 256) = make_float2(va0.y, va0.y);
        *reinterpret_cast<float2*>(pA + 2 * 256) = make_float2(va0.z, va0.z);
        *reinterpret_cast<float2*>(pA + 3 * 256) = make_float2(va0.w, va0.w);
        *reinterpret_cast<float2*>(pA + 4 * 256) = make_float2(va1.x, va1.x);
        *reinterpret_cast<float2*>(pA + 5 * 256) = make_float2(va1.y, va1.y);
        *reinterpret_cast<float2*>(pA + 6 * 256) = make_float2(va1.z, va1.z);
        *reinterpret_cast<float2*>(pA + 7 * 256) = make_float2(va1.w, va1.w);
        float* pB = sB + (size_t)kseg * 256 + rowA;
        pB[0 * 256] = vb0.x; pB[1 * 256] = vb0.y;
        pB[2 * 256] = vb0.z; pB[3 * 256] = vb0.w;
        pB[4 * 256] = vb1.x; pB[5 * 256] = vb1.y;
        pB[6 * 256] = vb1.z; pB[7 * 256] = vb1.w;
        float* pB2 = pB + 128;
        pB2[0 * 256] = vb2.x; pB2[1 * 256] = vb2.y;
        pB2[2 * 256] = vb2.z; pB2[3 * 256] = vb2.w;
        pB2[4 * 256] = vb3.x; pB2[5 * 256] = vb3.y;
        pB2[6 * 256] = vb3.z; pB2[7 * 256] = vb3.w;
    }
    __syncthreads();

    const int tx = t & 15, ty = t >> 4;
    const int m0 = ty * 8;

    unsigned long long acc[8][8];
#pragma unroll
    for (int i = 0; i < 8; i++)
#pragma unroll
        for (int j = 0; j < 8; j++) acc[i][j] = 0ULL;

    const int KT = K / BKT;
    const int bufStride = BKT * 256;
#pragma unroll 1
    for (int s = 0; s < KT; s++) {
        const int buf = s & 1;
        const bool more = (s + 1 < KT);
        if (more) {
            const size_t k1 = (size_t)(s + 1) * BKT;
            va0 = *reinterpret_cast<const float4*>(A + aOff + k1);
            va1 = *reinterpret_cast<const float4*>(A + aOff + k1 + 4);
            vb0 = *reinterpret_cast<const float4*>(Bsel + bOff0 + k1);
            vb1 = *reinterpret_cast<const float4*>(Bsel + bOff0 + k1 + 4);
            vb2 = *reinterpret_cast<const float4*>(Bsel + bOff1 + k1);
            vb3 = *reinterpret_cast<const float4*>(Bsel + bOff1 + k1 + 4);
        }

        const float* sAb = sAd + (size_t)buf * bufStride;
        const float* sBb = sB  + (size_t)buf * bufStride;

#pragma unroll
        for (int kk = 0; kk < BKT; kk++) {
            const float* pa = sAb + kk * 256 + 2 * m0;
            ulonglong2 A0 = *reinterpret_cast<const ulonglong2*>(pa);
            ulonglong2 A1 = *reinterpret_cast<const ulonglong2*>(pa + 4);
            ulonglong2 A2 = *reinterpret_cast<const ulonglong2*>(pa + 8);
            ulonglong2 A3 = *reinterpret_cast<const ulonglong2*>(pa + 12);
            const float* pb = sBb + kk * 256 + 2 * tx;
            unsigned long long bb[8];
#pragma unroll
            for (int j = 0; j < 8; j++)
                bb[j] = *reinterpret_cast<const unsigned long long*>(pb + 32 * j);

            unsigned long long aa[8];
            aa[0] = A0.x; aa[1] = A0.y; aa[2] = A1.x; aa[3] = A1.y;
            aa[4] = A2.x; aa[5] = A2.y; aa[6] = A3.x; aa[7] = A3.y;
#pragma unroll
            for (int i = 0; i < 8; i++)
#pragma unroll
                for (int j = 0; j < 8; j++)
                    FMA2(acc[i][j], aa[i], bb[j]);
        }

        if (more) {
            const int nb = buf ^ 1;
            float* pA = sAd + (size_t)nb * bufStride + kseg * 256 + 2 * rowA;
            *reinterpret_cast<float2*>(pA + 0 * 256) = make_float2(va0.x, va0.x);
            *reinterpret_cast<float2*>(pA + 1 * 256) = make_float2(va0.y, va0.y);
            *reinterpret_cast<float2*>(pA + 2 * 256) = make_float2(va0.z, va0.z);
            *reinterpret_cast<float2*>(pA + 3 * 256) = make_float2(va0.w, va0.w);
            *reinterpret_cast<float2*>(pA + 4 * 256) = make_float2(va1.x, va1.x);
            *reinterpret_cast<float2*>(pA + 5 * 256) = make_float2(va1.y, va1.y);
            *reinterpret_cast<float2*>(pA + 6 * 256) = make_float2(va1.z, va1.z);
            *reinterpret_cast<float2*>(pA + 7 * 256) = make_float2(va1.w, va1.w);
            float* pB = sB + (size_t)nb * bufStride + kseg * 256 + rowA;
            pB[0 * 256] = vb0.x; pB[1 * 256] = vb0.y;
            pB[2 * 256] = vb0.z; pB[3 * 256] = vb0.w;
            pB[4 * 256] = vb1.x; pB[5 * 256] = vb1.y;
            pB[6 * 256] = vb1.z; pB[7 * 256] = vb1.w;
            float* pB2 = pB + 128;
            pB2[0 * 256] = vb2.x; pB2[1 * 256] = vb2.y;
            pB2[2 * 256] = vb2.z; pB2[3 * 256] = vb2.w;
            pB2[4 * 256] = vb3.x; pB2[5 * 256] = vb3.y;
            pB2[6 * 256] = vb3.z; pB2[7 * 256] = vb3.w;
            __syncthreads();
        }
    }

    float2 bv[8];
#pragma unroll
    for (int j = 0; j < 8; j++)
        bv[j] = *reinterpret_cast<const float2*>(&bs[nrow + 2 * tx + 32 * j]);

#pragma unroll
    for (int i = 0; i < 8; i++) {
        float* orow = o + (size_t)(mBase + m0 + i) * ostride + nrow + 2 * tx;
#pragma unroll
        for (int j = 0; j < 8; j++) {
            float lo, hi;
            unpack2(acc[i][j], lo, hi);
            lo = __fadd_rn(lo, bv[j].x);
            hi = __fadd_rn(hi, bv[j].y);
            if (MODE == 0) {
                if (sig) { lo = sigmoid_ref(lo); hi = sigmoid_ref(hi); }
                else     { lo = fmaxf(lo, 0.0f); hi = fmaxf(hi, 0.0f); }
            }
            *reinterpret_cast<float2*>(orow + 32 * j) = make_float2(lo, hi);
        }
    }
}

// ---------------- layer-1 recurrence (float2, strict rn, in-place; R10) -----
__global__ void rec1_kernel(float2* cf, float2* fm)
{
    const int i = blockIdx.x * blockDim.x + threadIdx.x;   // < B*NH/2
    float2 syn = make_float2(0.f, 0.f), mem = make_float2(0.f, 0.f);
    size_t off = i;
    const size_t stride = (size_t)B_SZ * NH / 2;
#pragma unroll 2
    for (int t = 0; t < T_STEPS; t++, off += stride) {
        float2 c = cf[off];
        float2 f = fm[off];
        syn.x = __fadd_rn(__fmul_rn(f.x, syn.x), __fmul_rn(__fsub_rn(1.f, f.x), c.x));
        syn.y = __fadd_rn(__fmul_rn(f.y, syn.y), __fmul_rn(__fsub_rn(1.f, f.y), c.y));
        float spx = (__fsub_rn(mem.x, 1.0f) > 0.0f) ? 1.f : 0.f;
        float spy = (__fsub_rn(mem.y, 1.0f) > 0.0f) ? 1.f : 0.f;
        mem.x = __fsub_rn(__fadd_rn(__fmul_rn(0.5f, mem.x), syn.x), spx);
        mem.y = __fsub_rn(__fadd_rn(__fmul_rn(0.5f, mem.y), syn.y), spy);
        cf[off] = make_float2(spx, spy);
        fm[off] = mem;
    }
}

// ---------------- layer-2 recurrence (R10) -----------------------------------
__global__ void rec2_kernel(float* is, float* __restrict__ mo)
{
    const int i = blockIdx.x * blockDim.x + threadIdx.x;   // < B*NO
    float syn = 0.f, mem = 0.f;
    size_t off = i;
#pragma unroll 1
    for (int t = 0; t < T_STEPS; t++, off += (size_t)B_SZ * NO) {
        float inp = is[off];
        float m = __fsub_rn(mem, 1.0f);
        float spk = (m > 0.0f) ? 1.f : 0.f;
        syn = __fadd_rn(__fmul_rn(0.5f, syn), inp);
        mem = __fsub_rn(__fadd_rn(__fmul_rn(0.5f, mem), syn), spk);
        is[off] = spk;
        mo[off] = mem;
    }
}

// ---------------- launch ------------------------------------------------------
extern "C" void kernel_launch(void* const* d_in, const int* in_sizes, int n_in,
                              void* d_out, int out_size)
{
    const float* x  = (const float*)d_in[0];
    const float* W1 = (const float*)d_in[1];
    const float* b1 = (const float*)d_in[2];
    const float* Wr = (const float*)d_in[3];
    const float* br = (const float*)d_in[4];
    const float* W2 = (const float*)d_in[5];
    const float* b2 = (const float*)d_in[6];

    float* out = (float*)d_out;
    float* cand_spk1 = out;                                     // [T*B, NH]
    float* forg_mem1 = out + (size_t)MROWS * NH;                // [T*B, NH]
    float* inp2_spk2 = out + 2 * (size_t)MROWS * NH;            // [T*B, NO]
    float* mem2      = inp2_spk2 + (size_t)MROWS * NO;          // [T*B, NO]

    const int smemBytes = 2 * BKT * (2 * BM + BN) * (int)sizeof(float);  // 64 KB
    static bool attrSet = false;
    if (!attrSet) {
        cudaFuncSetAttribute(gemm_big<0>,
                             cudaFuncAttributeMaxDynamicSharedMemorySize, smemBytes);
        cudaFuncSetAttribute(gemm_big<1>,
                             cudaFuncAttributeMaxDynamicSharedMemorySize, smemBytes);
        attrSet = true;
    }

    // 1) GEMM1: cand = sigmoid(x@W1.T+b1), forget = relu(x@Wr.T+br)
    gemm_big<0><<<dim3(2 * NH / BN, MROWS / BM), 256, smemBytes>>>(
        x, W1, Wr, NI, b1, br, cand_spk1, forg_mem1);

    // 2) layer-1 scan (in-place, float2, unroll 2; R10)
    rec1_kernel<<<(B_SZ * NH / 2) / 256, 256>>>(
        (float2*)cand_spk1, (float2*)forg_mem1);

    // 3) GEMM2: inp2 = spk1@W2.T + b2 -> spk2 region
    gemm_big<1><<<dim3(NO / BN, MROWS / BM), 256, smemBytes>>>(
        cand_spk1, W2, nullptr, NH, b2, nullptr, inp2_spk2, nullptr);

    // 4) layer-2 scan (in-place: inp2->spk2)
    rec2_kernel<<<(B_SZ * NO) / 256, 256>>>(inp2_spk2, mem2);

    (void)in_sizes; (void)n_in; (void)out_size;
}

// round 16
// speedup vs baseline: 1.0924x; 1.0245x over previous
#include <cuda_runtime.h>
#include <math.h>

#define T_STEPS 128
#define B_SZ    256
#define NI      1024
#define NH      2048
#define NO      256
#define MROWS   (T_STEPS * B_SZ)   // 32768

// ---------------- packed f32x2 helpers (sm_100+) ----------------------------
__device__ __forceinline__ void unpack2(unsigned long long v, float& x, float& y)
{
    asm("mov.b64 {%0, %1}, %2;" : "=f"(x), "=f"(y) : "l"(v));
}
#define FMA2(acc, a, b) \
    asm("fma.rn.f32x2 %0, %1, %2, %0;" : "+l"(acc) : "l"(a), "l"(b))

// ---------------- reference sigmoid: Eigen/Cephes pexp with fmaf ------------
__device__ __forceinline__ float expf_cephes(float x)
{
    x = fminf(fmaxf(x, -88.723164f), 88.723164f);
    float m = floorf(fmaf(x, 1.44269504088896341f, 0.5f));
    float r = fmaf(m, -0.693359375f, x);
    r = fmaf(m, 2.12194440e-4f, r);
    float r2 = __fmul_rn(r, r);
    float r3 = __fmul_rn(r2, r);
    float y  = fmaf(1.9875691500E-4f, r, 1.3981999507E-3f);
    float y1 = fmaf(4.1665795894E-2f, r, 1.6666665459E-1f);
    float y2 = __fadd_rn(r, 1.0f);
    y  = fmaf(y, r, 8.3334519073E-3f);
    y1 = fmaf(y1, r, 5.0000001201E-1f);
    y  = fmaf(y, r3, y1);
    y  = fmaf(y, r2, y2);
    int e = (int)m;
    return __fmul_rn(y, __int_as_float((e + 127) << 23));
}

__device__ __forceinline__ float sigmoid_ref(float z)
{
    float e = expf_cephes(-z);
    return __fdiv_rn(1.0f, __fadd_rn(1.0f, e));
}

// ---------------- fp32 chain GEMM, 128x256 block, 8x16 thread tile ----------
// out[r][n] = chain_k fma.rn(A[r][k], B[n][k]), k ascending, single acc ->
// bit-identical to the validated chain (R10 configuration, byte-exact).
// MODE 0: grid.x 0..7 -> B0=W1, sigmoid -> out0 ; 8..15 -> B1=Wr, relu -> out1
// MODE 1: grid.x == 0 -> B0=W2, bias only -> out0
#define BKT 16
#define BM  128
#define BN  256

template <int MODE>
__global__ __launch_bounds__(256)
void gemm_big(const float* __restrict__ A,
              const float* __restrict__ B0, const float* __restrict__ B1,
              int K,
              const float* __restrict__ bias0, const float* __restrict__ bias1,
              float* __restrict__ out0, float* __restrict__ out1)
{
    extern __shared__ float sh[];
    float* sAd = sh;                       // [2][BKT][2*BM]  (A rows duplicated)
    float* sB  = sh + 2 * BKT * 2 * BM;    // [2][BKT][BN]

    const int t     = threadIdx.x;
    const int mBase = blockIdx.y * BM;
    const int nBase = blockIdx.x * BN;

    bool sig;
    const float* Bsel;
    const float* bs;
    float* o;
    int nrow, ostride;
    if (MODE == 0) {
        sig     = (nBase < NH);
        Bsel    = sig ? B0 : B1;
        nrow    = sig ? nBase : (nBase - NH);
        bs      = sig ? bias0 : bias1;
        o       = sig ? out0 : out1;
        ostride = NH;
    } else {
        sig = false; Bsel = B0; nrow = nBase; bs = bias0; o = out0; ostride = NO;
    }

    const int rowA = t >> 1;
    const int kseg = (t & 1) * 8;
    const size_t aOff  = (size_t)(mBase + rowA) * K + kseg;
    const size_t bOff0 = (size_t)(nrow + rowA) * K + kseg;
    const size_t bOff1 = (size_t)(nrow + rowA + 128) * K + kseg;

    float4 va0 = *reinterpret_cast<const float4*>(A + aOff);
    float4 va1 = *reinterpret_cast<const float4*>(A + aOff + 4);
    float4 vb0 = *reinterpret_cast<const float4*>(Bsel + bOff0);
    float4 vb1 = *reinterpret_cast<const float4*>(Bsel + bOff0 + 4);
    float4 vb2 = *reinterpret_cast<const float4*>(Bsel + bOff1);
    float4 vb3 = *reinterpret_cast<const float4*>(Bsel + bOff1 + 4);

    {
        float* pA = sAd + (size_t)kseg * 256 + 2 * rowA;
        *reinterpret_cast<float2*>(pA + 0 * 256) = make_float2(va0.x, va0.x);
        *reinterpret_cast<float2*>(pA + 1 * 256) = make_float2(va0.y, va0.y);
        *reinterpret_cast<float2*>(pA + 2 * 256) = make_float2(va0.z, va0.z);
        *reinterpret_cast<float2*>(pA + 3 * 256) = make_float2(va0.w, va0.w);
        *reinterpret_cast<float2*>(pA + 4 * 256) = make_float2(va1.x, va1.x);
        *reinterpret_cast<float2*>(pA + 5 * 256) = make_float2(va1.y, va1.y);
        *reinterpret_cast<float2*>(pA + 6 * 256) = make_float2(va1.z, va1.z);
        *reinterpret_cast<float2*>(pA + 7 * 256) = make_float2(va1.w, va1.w);
        float* pB = sB + (size_t)kseg * 256 + rowA;
        pB[0 * 256] = vb0.x; pB[1 * 256] = vb0.y;
        pB[2 * 256] = vb0.z; pB[3 * 256] = vb0.w;
        pB[4 * 256] = vb1.x; pB[5 * 256] = vb1.y;
        pB[6 * 256] = vb1.z; pB[7 * 256] = vb1.w;
        float* pB2 = pB + 128;
        pB2[0 * 256] = vb2.x; pB2[1 * 256] = vb2.y;
        pB2[2 * 256] = vb2.z; pB2[3 * 256] = vb2.w;
        pB2[4 * 256] = vb3.x; pB2[5 * 256] = vb3.y;
        pB2[6 * 256] = vb3.z; pB2[7 * 256] = vb3.w;
    }
    __syncthreads();

    const int tx = t & 15, ty = t >> 4;
    const int m0 = ty * 8;

    unsigned long long acc[8][8];
#pragma unroll
    for (int i = 0; i < 8; i++)
#pragma unroll
        for (int j = 0; j < 8; j++) acc[i][j] = 0ULL;

    const int KT = K / BKT;
    const int bufStride = BKT * 256;
#pragma unroll 1
    for (int s = 0; s < KT; s++) {
        const int buf = s & 1;
        const bool more = (s + 1 < KT);
        if (more) {
            const size_t k1 = (size_t)(s + 1) * BKT;
            va0 = *reinterpret_cast<const float4*>(A + aOff + k1);
            va1 = *reinterpret_cast<const float4*>(A + aOff + k1 + 4);
            vb0 = *reinterpret_cast<const float4*>(Bsel + bOff0 + k1);
            vb1 = *reinterpret_cast<const float4*>(Bsel + bOff0 + k1 + 4);
            vb2 = *reinterpret_cast<const float4*>(Bsel + bOff1 + k1);
            vb3 = *reinterpret_cast<const float4*>(Bsel + bOff1 + k1 + 4);
        }

        const float* sAb = sAd + (size_t)buf * bufStride;
        const float* sBb = sB  + (size_t)buf * bufStride;

#pragma unroll
        for (int kk = 0; kk < BKT; kk++) {
            const float* pa = sAb + kk * 256 + 2 * m0;
            ulonglong2 A0 = *reinterpret_cast<const ulonglong2*>(pa);
            ulonglong2 A1 = *reinterpret_cast<const ulonglong2*>(pa + 4);
            ulonglong2 A2 = *reinterpret_cast<const ulonglong2*>(pa + 8);
            ulonglong2 A3 = *reinterpret_cast<const ulonglong2*>(pa + 12);
            const float* pb = sBb + kk * 256 + 2 * tx;
            unsigned long long bb[8];
#pragma unroll
            for (int j = 0; j < 8; j++)
                bb[j] = *reinterpret_cast<const unsigned long long*>(pb + 32 * j);

            unsigned long long aa[8];
            aa[0] = A0.x; aa[1] = A0.y; aa[2] = A1.x; aa[3] = A1.y;
            aa[4] = A2.x; aa[5] = A2.y; aa[6] = A3.x; aa[7] = A3.y;
#pragma unroll
            for (int i = 0; i < 8; i++)
#pragma unroll
                for (int j = 0; j < 8; j++)
                    FMA2(acc[i][j], aa[i], bb[j]);
        }

        if (more) {
            const int nb = buf ^ 1;
            float* pA = sAd + (size_t)nb * bufStride + kseg * 256 + 2 * rowA;
            *reinterpret_cast<float2*>(pA + 0 * 256) = make_float2(va0.x, va0.x);
            *reinterpret_cast<float2*>(pA + 1 * 256) = make_float2(va0.y, va0.y);
            *reinterpret_cast<float2*>(pA + 2 * 256) = make_float2(va0.z, va0.z);
            *reinterpret_cast<float2*>(pA + 3 * 256) = make_float2(va0.w, va0.w);
            *reinterpret_cast<float2*>(pA + 4 * 256) = make_float2(va1.x, va1.x);
            *reinterpret_cast<float2*>(pA + 5 * 256) = make_float2(va1.y, va1.y);
            *reinterpret_cast<float2*>(pA + 6 * 256) = make_float2(va1.z, va1.z);
            *reinterpret_cast<float2*>(pA + 7 * 256) = make_float2(va1.w, va1.w);
            float* pB = sB + (size_t)nb * bufStride + kseg * 256 + rowA;
            pB[0 * 256] = vb0.x; pB[1 * 256] = vb0.y;
            pB[2 * 256] = vb0.z; pB[3 * 256] = vb0.w;
            pB[4 * 256] = vb1.x; pB[5 * 256] = vb1.y;
            pB[6 * 256] = vb1.z; pB[7 * 256] = vb1.w;
            float* pB2 = pB + 128;
            pB2[0 * 256] = vb2.x; pB2[1 * 256] = vb2.y;
            pB2[2 * 256] = vb2.z; pB2[3 * 256] = vb2.w;
            pB2[4 * 256] = vb3.x; pB2[5 * 256] = vb3.y;
            pB2[6 * 256] = vb3.z; pB2[7 * 256] = vb3.w;
            __syncthreads();
        }
    }

    float2 bv[8];
#pragma unroll
    for (int j = 0; j < 8; j++)
        bv[j] = *reinterpret_cast<const float2*>(&bs[nrow + 2 * tx + 32 * j]);

#pragma unroll
    for (int i = 0; i < 8; i++) {
        float* orow = o + (size_t)(mBase + m0 + i) * ostride + nrow + 2 * tx;
#pragma unroll
        for (int j = 0; j < 8; j++) {
            float lo, hi;
            unpack2(acc[i][j], lo, hi);
            lo = __fadd_rn(lo, bv[j].x);
            hi = __fadd_rn(hi, bv[j].y);
            if (MODE == 0) {
                if (sig) { lo = sigmoid_ref(lo); hi = sigmoid_ref(hi); }
                else     { lo = fmaxf(lo, 0.0f); hi = fmaxf(hi, 0.0f); }
            }
            *reinterpret_cast<float2*>(orow + 32 * j) = make_float2(lo, hi);
        }
    }
}

// ---------------- layer-1 recurrence (float2, restrict, unroll 4) -----------
// cf (cand->spk1) and fm (forget->mem1) are provably disjoint d_out regions;
// __restrict__ lets ptxas hoist next-step loads above this step's stores.
__global__ void rec1_kernel(float2* __restrict__ cf, float2* __restrict__ fm)
{
    const int i = blockIdx.x * blockDim.x + threadIdx.x;   // < B*NH/2
    float2 syn = make_float2(0.f, 0.f), mem = make_float2(0.f, 0.f);
    size_t off = i;
    const size_t stride = (size_t)B_SZ * NH / 2;
#pragma unroll 4
    for (int t = 0; t < T_STEPS; t++, off += stride) {
        float2 c = cf[off];
        float2 f = fm[off];
        syn.x = __fadd_rn(__fmul_rn(f.x, syn.x), __fmul_rn(__fsub_rn(1.f, f.x), c.x));
        syn.y = __fadd_rn(__fmul_rn(f.y, syn.y), __fmul_rn(__fsub_rn(1.f, f.y), c.y));
        float spx = (__fsub_rn(mem.x, 1.0f) > 0.0f) ? 1.f : 0.f;
        float spy = (__fsub_rn(mem.y, 1.0f) > 0.0f) ? 1.f : 0.f;
        mem.x = __fsub_rn(__fadd_rn(__fmul_rn(0.5f, mem.x), syn.x), spx);
        mem.y = __fsub_rn(__fadd_rn(__fmul_rn(0.5f, mem.y), syn.y), spy);
        cf[off] = make_float2(spx, spy);
        fm[off] = mem;
    }
}

// ---------------- layer-2 recurrence (restrict, unroll 4) -------------------
__global__ void rec2_kernel(float* __restrict__ is, float* __restrict__ mo)
{
    const int i = blockIdx.x * blockDim.x + threadIdx.x;   // < B*NO
    float syn = 0.f, mem = 0.f;
    size_t off = i;
#pragma unroll 4
    for (int t = 0; t < T_STEPS; t++, off += (size_t)B_SZ * NO) {
        float inp = is[off];
        float m = __fsub_rn(mem, 1.0f);
        float spk = (m > 0.0f) ? 1.f : 0.f;
        syn = __fadd_rn(__fmul_rn(0.5f, syn), inp);
        mem = __fsub_rn(__fadd_rn(__fmul_rn(0.5f, mem), syn), spk);
        is[off] = spk;
        mo[off] = mem;
    }
}

// ---------------- launch ------------------------------------------------------
extern "C" void kernel_launch(void* const* d_in, const int* in_sizes, int n_in,
                              void* d_out, int out_size)
{
    const float* x  = (const float*)d_in[0];
    const float* W1 = (const float*)d_in[1];
    const float* b1 = (const float*)d_in[2];
    const float* Wr = (const float*)d_in[3];
    const float* br = (const float*)d_in[4];
    const float* W2 = (const float*)d_in[5];
    const float* b2 = (const float*)d_in[6];

    float* out = (float*)d_out;
    float* cand_spk1 = out;                                     // [T*B, NH]
    float* forg_mem1 = out + (size_t)MROWS * NH;                // [T*B, NH]
    float* inp2_spk2 = out + 2 * (size_t)MROWS * NH;            // [T*B, NO]
    float* mem2      = inp2_spk2 + (size_t)MROWS * NO;          // [T*B, NO]

    const int smemBytes = 2 * BKT * (2 * BM + BN) * (int)sizeof(float);  // 64 KB
    static bool attrSet = false;
    if (!attrSet) {
        cudaFuncSetAttribute(gemm_big<0>,
                             cudaFuncAttributeMaxDynamicSharedMemorySize, smemBytes);
        cudaFuncSetAttribute(gemm_big<1>,
                             cudaFuncAttributeMaxDynamicSharedMemorySize, smemBytes);
        attrSet = true;
    }

    // 1) GEMM1: cand = sigmoid(x@W1.T+b1), forget = relu(x@Wr.T+br)
    gemm_big<0><<<dim3(2 * NH / BN, MROWS / BM), 256, smemBytes>>>(
        x, W1, Wr, NI, b1, br, cand_spk1, forg_mem1);

    // 2) layer-1 scan (in-place, float2, restrict+unroll4)
    rec1_kernel<<<(B_SZ * NH / 2) / 256, 256>>>(
        (float2*)cand_spk1, (float2*)forg_mem1);

    // 3) GEMM2: inp2 = spk1@W2.T + b2 -> spk2 region
    gemm_big<1><<<dim3(NO / BN, MROWS / BM), 256, smemBytes>>>(
        cand_spk1, W2, nullptr, NH, b2, nullptr, inp2_spk2, nullptr);

    // 4) layer-2 scan (in-place: inp2->spk2, restrict+unroll4)
    rec2_kernel<<<(B_SZ * NO) / 256, 256>>>(inp2_spk2, mem2);

    (void)in_sizes; (void)n_in; (void)out_size;
}